// round 14
// baseline (speedup 1.0000x reference)
#include <cuda_runtime.h>
#include <cstdint>

#define S_LEN 2048
#define BATCH 128
#define IN_DIM 64
#define HID 128
#define G4 512
#define OUT_DIM 64
#define NGROUP 32
#define CPG 4
#define BG 4
#define NCTA (NGROUP * CPG)

// ---- static device scratch ----
__device__ float g_Xp[(size_t)S_LEN * BATCH * G4];   // [s][b][n]
__device__ float g_hs[(size_t)S_LEN * BATCH * HID];  // [s][b][h]
__device__ int g_dummy;

#define OUT_SMEM ((128 * 136 + 128 * 65) * 4)

__device__ __forceinline__ float sigf(float v) {
    return __fdividef(1.f, 1.f + __expf(-v));
}
__device__ __forceinline__ float tanhf_fast(float x) {
    float cx = fminf(fmaxf(x, -15.f), 15.f);
    float e = __expf(2.f * cx);
    return __fdividef(e - 1.f, e + 1.f);
}

__device__ __forceinline__ uint32_t smem_u32(const void* p) {
    uint32_t a;
    asm("{ .reg .u64 t; cvta.to.shared.u64 t, %1; cvt.u32.u64 %0, t; }" : "=r"(a) : "l"(p));
    return a;
}
__device__ __forceinline__ uint32_t mapa_u32(uint32_t local_addr, int rank) {
    uint32_t r;
    asm("mapa.shared::cluster.u32 %0, %1, %2;" : "=r"(r) : "r"(local_addr), "r"(rank));
    return r;
}
#define CLUSTER_SYNC_() do { \
    asm volatile("barrier.cluster.arrive.aligned;" ::: "memory"); \
    asm volatile("barrier.cluster.wait.aligned;" ::: "memory"); \
} while (0)

#define MBAR_INIT(addr, cnt) \
    asm volatile("mbarrier.init.shared.b64 [%0], %1;" :: "r"(addr), "r"(cnt) : "memory")
#define MBAR_ARM(addr, bytes) \
    asm volatile("mbarrier.arrive.expect_tx.shared.b64 _, [%0], %1;" :: "r"(addr), "r"(bytes) : "memory")
#define MBAR_WAIT(addr, parity) do { \
    asm volatile("{\n\t.reg .pred P1;\n\t" \
        "WAIT_%=:\n\t" \
        "mbarrier.try_wait.parity.acquire.cta.shared::cta.b64 P1, [%0], %1, 0x989680;\n\t" \
        "@P1 bra.uni DONE_%=;\n\t" \
        "bra.uni WAIT_%=;\n\t" \
        "DONE_%=:\n\t}" \
        :: "r"(addr), "r"(parity) : "memory"); \
} while (0)

__device__ __forceinline__ void st_async_u64(uint32_t daddr, uint32_t dmbar, unsigned long long v) {
    asm volatile("st.async.shared::cluster.mbarrier::complete_tx::bytes.b64 [%0], %1, [%2];"
                 :: "r"(daddr), "l"(v), "r"(dmbar) : "memory");
}

__device__ __forceinline__ void ffma2(unsigned long long& d, unsigned long long a, unsigned long long b) {
    asm("fma.rn.f32x2 %0, %1, %2, %0;" : "+l"(d) : "l"(a), "l"(b));
}
__device__ __forceinline__ unsigned long long pack2(float a, float b) {
    unsigned long long p;
    asm("mov.b64 %0, {%1, %2};" : "=l"(p) : "f"(a), "f"(b));
    return p;
}

// ---- dummy: keeps rec_kernel at process launch #4 for ncu capture ----
__global__ void dummy_kernel(int v) {
    if (threadIdx.x == 0 && blockIdx.x == 0) g_dummy = v;
}

// ---- Kernel 1: Xp[s][b][n] = b_out[n] + sum_i x[b][i][s] * Wx_out[i][n] ----
__global__ __launch_bounds__(256) void xproj_kernel(const float* __restrict__ x,
                                                    const float* __restrict__ Wx,
                                                    const float* __restrict__ bo) {
    __shared__ float xs[IN_DIM * 33];
    const int s = blockIdx.x;
    const int b0 = blockIdx.y * 32;
    const int t = threadIdx.x;
    const int b = t & 31;
    const int n0 = (t >> 5) * 64;

    for (int q = t; q < 32 * IN_DIM; q += 256) {
        int bb = q >> 6, i = q & 63;
        xs[i * 33 + bb] = x[((size_t)(b0 + bb) * IN_DIM + i) * S_LEN + s];
    }
    __syncthreads();

    float acc[64];
#pragma unroll
    for (int j = 0; j < 64; j++) acc[j] = 0.f;
#pragma unroll 2
    for (int k = 0; k < IN_DIM; k++) {
        float xv = xs[k * 33 + b];
        const float4* wr = (const float4*)(Wx + (size_t)k * G4 + n0);
#pragma unroll
        for (int j4 = 0; j4 < 16; j4++) {
            float4 w = __ldg(&wr[j4]);
            acc[4 * j4 + 0] = fmaf(xv, w.x, acc[4 * j4 + 0]);
            acc[4 * j4 + 1] = fmaf(xv, w.y, acc[4 * j4 + 1]);
            acc[4 * j4 + 2] = fmaf(xv, w.z, acc[4 * j4 + 2]);
            acc[4 * j4 + 3] = fmaf(xv, w.w, acc[4 * j4 + 3]);
        }
    }
#pragma unroll
    for (int j = 0; j < 64; j++) {
        g_Xp[((size_t)s * BATCH + b0 + b) * G4 + n0 + j] = acc[j] + __ldg(&bo[n0 + j]);
    }
}

// ---- Kernel 2: persistent recurrence, K-sliced partial-exchange dataflow.
//      CTA cs computes partials over ITS OWN k-slice (produced locally) for ALL
//      512 gate cols; partials st.async'd to column owners AFTER the GEMM.
//      No pre-GEMM cross-CTA wait. ----
__global__ __launch_bounds__(256, 1) __cluster_dims__(CPG, 1, 1)
void rec_kernel(const float* __restrict__ Wh_out,
                const float* __restrict__ Wx_in,
                const float* __restrict__ Wh_in,
                const float* __restrict__ b_in) {
    __shared__ __align__(16) float sh_h2[BG * 64];    // [r][kk<16][4]: {h2kk,h2kk,h2kk+1,h2kk+1}
    __shared__ __align__(16) float sh_x2[BG * 128];   // [r][m<32][4]:  {xin,xin,hin,hin}
    __shared__ __align__(16) float pbo[4 * 4 * 128];  // outer partials [src][r][gt*32+hc]
    __shared__ __align__(16) float pbi[4 * 4 * 128];  // inner partials, same layout
    __shared__ __align__(8) unsigned long long mbars[2];  // [0]=outer, [1]=inner
    __shared__ uint32_t ptab[CPG * 4];                // per rank: pbo, pbi, bo, bi

    const int cta = blockIdx.x;
    const int g   = cta >> 2;
    const int t   = threadIdx.x;
    uint32_t cs;
    asm("mov.u32 %0, %%cluster_ctarank;" : "=r"(cs));

    // GEMM-thread column pair: c0 = 2t, c1 = 2t+1 (never cross a gate boundary)
    const int c0 = 2 * t;
    const int gt0 = c0 >> 7;
    const int ii = c0 & 127;
    const int dest = ii >> 5;            // owner rank of both cols
    const int i_loc = ii & 31;           // even
    // float offset inside owner's partial buffer (row r adds r*128)
    const int poff = gt0 * 32 + i_loc;

    // ---- register-resident weights for my k-slice, col-pair packed ----
    unsigned long long wo[32];   // k = cs*32 + k_loc -> {Wh_out[k][c0], Wh_out[k][c1]}
    unsigned long long wi[64];   // k' = cs*64 + kp -> {W[h][c0], W[h][c1]}, W = even? Wx_in : Wh_in
    {
#pragma unroll
        for (int kl = 0; kl < 32; kl++) {
            const float* wr = Wh_out + (size_t)((int)cs * 32 + kl) * G4;
            wo[kl] = pack2(wr[c0], wr[c0 + 1]);
        }
#pragma unroll
        for (int kp = 0; kp < 64; kp++) {
            int h = ((int)cs * 64 + kp) >> 1;
            const float* wr = ((kp & 1) ? Wh_in : Wx_in) + (size_t)h * G4;
            wi[kp] = pack2(wr[c0], wr[c0 + 1]);
        }
    }

    // peer address table + mbarrier init/arm
    if (t < CPG) {
        ptab[t * 4 + 0] = mapa_u32(smem_u32(pbo), t);
        ptab[t * 4 + 1] = mapa_u32(smem_u32(pbi), t);
        ptab[t * 4 + 2] = mapa_u32(smem_u32(&mbars[0]), t);
        ptab[t * 4 + 3] = mapa_u32(smem_u32(&mbars[1]), t);
    }
    const uint32_t bo_loc = smem_u32(&mbars[0]);
    const uint32_t bi_loc = smem_u32(&mbars[1]);
    if (t == 0) {
        MBAR_INIT(bo_loc, 1);
        MBAR_INIT(bi_loc, 1);
        MBAR_ARM(bo_loc, 8192u);   // 4 src x 64 thr x 4 rows x 8B
        MBAR_ARM(bi_loc, 8192u);
    }
    for (int q = t; q < BG * 64; q += 256) sh_h2[q] = 0.f;   // h0 = 0 (splatted)
    __syncthreads();
    CLUSTER_SYNC_();   // peers' mbars armed before any st.async

    // owner role (t < 128): batch row bl, own hidden col hc
    const int bl = t >> 5, hc = t & 31;
    const int h_own = (int)cs * 32 + hc;
    float c_reg = 0.f, cn_reg = 0.f, o_reg = 0.f;

    // sender destination byte bases (row stride 512B)
    const uint32_t sdo = ptab[dest * 4 + 0] + (uint32_t)(((int)cs * 4 * 128 + poff) * 4);
    const uint32_t sdi = ptab[dest * 4 + 1] + (uint32_t)(((int)cs * 4 * 128 + poff) * 4);
    const uint32_t smo = ptab[dest * 4 + 2];
    const uint32_t smi = ptab[dest * 4 + 3];

    for (int s = 0; s < S_LEN; s++) {
        const uint32_t par = (uint32_t)(s & 1);

        // ---- outer partial GEMM over my k-slice (local h, no wait) ----
        unsigned long long a0 = 0ull, a1 = 0ull, a2 = 0ull, a3 = 0ull;
#pragma unroll
        for (int kk = 0; kk < 16; kk++) {
            ulonglong2 h0 = *(const ulonglong2*)(sh_h2 + 0 * 64 + kk * 4);
            ulonglong2 h1 = *(const ulonglong2*)(sh_h2 + 1 * 64 + kk * 4);
            ulonglong2 h2 = *(const ulonglong2*)(sh_h2 + 2 * 64 + kk * 4);
            ulonglong2 h3 = *(const ulonglong2*)(sh_h2 + 3 * 64 + kk * 4);
            unsigned long long wA = wo[2 * kk], wB = wo[2 * kk + 1];
            ffma2(a0, h0.x, wA); ffma2(a0, h0.y, wB);
            ffma2(a1, h1.x, wA); ffma2(a1, h1.y, wB);
            ffma2(a2, h2.x, wA); ffma2(a2, h2.y, wB);
            ffma2(a3, h3.x, wA); ffma2(a3, h3.y, wB);
        }
        st_async_u64(sdo + 0u,    smo, a0);
        st_async_u64(sdo + 512u,  smo, a1);
        st_async_u64(sdo + 1024u, smo, a2);
        st_async_u64(sdo + 1536u, smo, a3);

        MBAR_WAIT(bo_loc, par);
        if (t == 0) MBAR_ARM(bo_loc, 8192u);

        // ---- owner: sum 4 partials + Xp, EW1, stage xh (splatted) ----
        if (t < 128) {
            const float* xp = g_Xp + ((size_t)s * BATCH + g * BG + bl) * G4 + (int)cs * 32 + hc;
            float gv[4];
#pragma unroll
            for (int gt = 0; gt < 4; gt++) {
                int o = bl * 128 + gt * 32 + hc;
                gv[gt] = pbo[o] + pbo[512 + o] + pbo[1024 + o] + pbo[1536 + o]
                       + __ldcs(xp + gt * HID);
            }
            float i_ = sigf(gv[0]);
            float f_ = sigf(gv[1]);
            o_reg    = sigf(gv[2]);
            float g_ = tanhf_fast(gv[3]);
            float xin = i_ * g_;
            float hin = f_ * c_reg;
            *(float4*)(sh_x2 + bl * 128 + hc * 4) = make_float4(xin, xin, hin, hin);
        }
        __syncthreads();

        // ---- inner partial GEMM over my k'-slice (local xh) ----
        a0 = a1 = a2 = a3 = 0ull;
#pragma unroll
        for (int m = 0; m < 32; m++) {
            ulonglong2 h0 = *(const ulonglong2*)(sh_x2 + 0 * 128 + m * 4);
            ulonglong2 h1 = *(const ulonglong2*)(sh_x2 + 1 * 128 + m * 4);
            ulonglong2 h2 = *(const ulonglong2*)(sh_x2 + 2 * 128 + m * 4);
            ulonglong2 h3 = *(const ulonglong2*)(sh_x2 + 3 * 128 + m * 4);
            unsigned long long wA = wi[2 * m], wB = wi[2 * m + 1];
            ffma2(a0, h0.x, wA); ffma2(a0, h0.y, wB);
            ffma2(a1, h1.x, wA); ffma2(a1, h1.y, wB);
            ffma2(a2, h2.x, wA); ffma2(a2, h2.y, wB);
            ffma2(a3, h3.x, wA); ffma2(a3, h3.y, wB);
        }
        st_async_u64(sdi + 0u,    smi, a0);
        st_async_u64(sdi + 512u,  smi, a1);
        st_async_u64(sdi + 1024u, smi, a2);
        st_async_u64(sdi + 1536u, smi, a3);

        MBAR_WAIT(bi_loc, par);
        if (t == 0) MBAR_ARM(bi_loc, 8192u);

        // ---- owner: sum, EW2, stage h (splatted), store g_hs ----
        if (t < 128) {
            float gv[4];
#pragma unroll
            for (int gt = 0; gt < 4; gt++) {
                int o = bl * 128 + gt * 32 + hc;
                gv[gt] = pbi[o] + pbi[512 + o] + pbi[1024 + o] + pbi[1536 + o]
                       + __ldg(&b_in[gt * 128 + (int)cs * 32 + hc]);
            }
            float ii = sigf(gv[0]);
            float fi = sigf(gv[1]);
            float oi = sigf(gv[2]);
            float gg = tanhf_fast(gv[3]);
            cn_reg = fi * cn_reg + ii * gg;
            c_reg  = oi * tanhf_fast(cn_reg);
            float hnew = o_reg * tanhf_fast(c_reg);
            *(unsigned long long*)(sh_h2 + bl * 64 + (hc >> 1) * 4 + (hc & 1) * 2) = pack2(hnew, hnew);
            g_hs[((size_t)s * BATCH + g * BG + bl) * HID + h_own] = hnew;
        }
        __syncthreads();
    }
    CLUSTER_SYNC_();
}

// ---- Kernel 3: out[b][s][o] = b_lin[o] + sum_h hs[s][b][h] * W_lin[o][h] ----
__global__ __launch_bounds__(256) void out_kernel(const float* __restrict__ Wl,
                                                  const float* __restrict__ bl,
                                                  float* __restrict__ out) {
    extern __shared__ float sm[];
    float* hsb = sm;               // transposed [h][b], pad 136
    float* wls = sm + 128 * 136;   // [h][o] pad 65

    const int s = blockIdx.x;
    const int t = threadIdx.x;
    const int o = t & 63;
    const int b0 = (t >> 6) * 32;

    const float* src = g_hs + (size_t)s * BATCH * HID;   // [b][h]
    for (int q = t; q < 16384; q += 256) {
        int b = q >> 7, h = q & 127;
        hsb[h * 136 + b] = src[q];
    }
    for (int q = t; q < 8192; q += 256) {
        int oo = q >> 7, k = q & 127;
        wls[k * 65 + oo] = Wl[q];
    }
    __syncthreads();

    float acc[32];
#pragma unroll
    for (int jj = 0; jj < 32; jj++) acc[jj] = 0.f;
#pragma unroll 2
    for (int k = 0; k < HID; k++) {
        float wv = wls[k * 65 + o];
        const float4* hr = (const float4*)(hsb + k * 136 + b0);
#pragma unroll
        for (int j4 = 0; j4 < 8; j4++) {
            float4 hv = hr[j4];
            acc[4 * j4 + 0] = fmaf(hv.x, wv, acc[4 * j4 + 0]);
            acc[4 * j4 + 1] = fmaf(hv.y, wv, acc[4 * j4 + 1]);
            acc[4 * j4 + 2] = fmaf(hv.z, wv, acc[4 * j4 + 2]);
            acc[4 * j4 + 3] = fmaf(hv.w, wv, acc[4 * j4 + 3]);
        }
    }
    float bb = bl[o];
#pragma unroll
    for (int jj = 0; jj < 32; jj++) {
        out[((size_t)(b0 + jj) * S_LEN + s) * OUT_DIM + o] = acc[jj] + bb;
    }
}

extern "C" void kernel_launch(void* const* d_in, const int* in_sizes, int n_in,
                              void* d_out, int out_size) {
    const float* x      = (const float*)d_in[0];
    const float* Wx_out = (const float*)d_in[1];
    const float* Wh_out = (const float*)d_in[2];
    const float* b_out  = (const float*)d_in[3];
    const float* Wx_in  = (const float*)d_in[4];
    const float* Wh_in  = (const float*)d_in[5];
    const float* b_in   = (const float*)d_in[6];
    const float* W_lin  = (const float*)d_in[7];
    const float* b_lin  = (const float*)d_in[8];
    float* out = (float*)d_out;

    cudaFuncSetAttribute(out_kernel, cudaFuncAttributeMaxDynamicSharedMemorySize, OUT_SMEM);

    dummy_kernel<<<1, 32>>>(1);                            // launch #1
    dummy_kernel<<<1, 32>>>(2);                            // launch #2
    xproj_kernel<<<dim3(S_LEN, BATCH / 32), 256>>>(x, Wx_out, b_out);  // #3
    rec_kernel<<<NCTA, 256>>>(Wh_out, Wx_in, Wh_in, b_in);             // #4 <- ncu slot
    out_kernel<<<S_LEN, 256, OUT_SMEM>>>(W_lin, b_lin, out);
}

// round 15
// speedup vs baseline: 1.2537x; 1.2537x over previous
#include <cuda_runtime.h>
#include <cstdint>

#define S_LEN 2048
#define BATCH 128
#define IN_DIM 64
#define HID 128
#define G4 512
#define OUT_DIM 64
#define NGROUP 32
#define CPG 4
#define BG 4
#define NCTA (NGROUP * CPG)

// ---- static device scratch ----
__device__ float g_Xp[(size_t)S_LEN * BATCH * G4];   // [s][b][n]
__device__ float g_hs[(size_t)S_LEN * BATCH * HID];  // [s][b][h]
__device__ int g_dummy;

#define OUT_SMEM ((128 * 136 + 128 * 65) * 4)

__device__ __forceinline__ float sigf(float v) {
    return __fdividef(1.f, 1.f + __expf(-v));
}
__device__ __forceinline__ float tanhf_fast(float x) {
    float cx = fminf(fmaxf(x, -15.f), 15.f);
    float e = __expf(2.f * cx);
    return __fdividef(e - 1.f, e + 1.f);
}

__device__ __forceinline__ uint32_t smem_u32(const void* p) {
    uint32_t a;
    asm("{ .reg .u64 t; cvta.to.shared.u64 t, %1; cvt.u32.u64 %0, t; }" : "=r"(a) : "l"(p));
    return a;
}
__device__ __forceinline__ uint32_t mapa_u32(uint32_t local_addr, int rank) {
    uint32_t r;
    asm("mapa.shared::cluster.u32 %0, %1, %2;" : "=r"(r) : "r"(local_addr), "r"(rank));
    return r;
}
#define CLUSTER_SYNC_() do { \
    asm volatile("barrier.cluster.arrive.aligned;" ::: "memory"); \
    asm volatile("barrier.cluster.wait.aligned;" ::: "memory"); \
} while (0)

#define MBAR_INIT(addr, cnt) \
    asm volatile("mbarrier.init.shared.b64 [%0], %1;" :: "r"(addr), "r"(cnt) : "memory")
#define MBAR_ARM(addr, bytes) \
    asm volatile("mbarrier.arrive.expect_tx.shared.b64 _, [%0], %1;" :: "r"(addr), "r"(bytes) : "memory")
#define MBAR_WAIT(addr, parity) do { \
    asm volatile("{\n\t.reg .pred P1;\n\t" \
        "WAIT_%=:\n\t" \
        "mbarrier.try_wait.parity.acquire.cta.shared::cta.b64 P1, [%0], %1, 0x989680;\n\t" \
        "@P1 bra.uni DONE_%=;\n\t" \
        "bra.uni WAIT_%=;\n\t" \
        "DONE_%=:\n\t}" \
        :: "r"(addr), "r"(parity) : "memory"); \
} while (0)

__device__ __forceinline__ void st_async_f32(uint32_t daddr, uint32_t dmbar, float v) {
    asm volatile("st.async.shared::cluster.mbarrier::complete_tx::bytes.f32 [%0], %1, [%2];"
                 :: "r"(daddr), "f"(v), "r"(dmbar) : "memory");
}
__device__ __forceinline__ void st_async_v2f32(uint32_t daddr, uint32_t dmbar, float a, float b) {
    asm volatile("st.async.shared::cluster.mbarrier::complete_tx::bytes.v2.f32 [%0], {%1, %2}, [%3];"
                 :: "r"(daddr), "f"(a), "f"(b), "r"(dmbar) : "memory");
}

__device__ __forceinline__ void ffma2(unsigned long long& d, unsigned long long a, unsigned long long b) {
    asm("fma.rn.f32x2 %0, %1, %2, %0;" : "+l"(d) : "l"(a), "l"(b));
}
__device__ __forceinline__ unsigned long long pack2(float a, float b) {
    unsigned long long p;
    asm("mov.b64 %0, {%1, %2};" : "=l"(p) : "f"(a), "f"(b));
    return p;
}
__device__ __forceinline__ float sum2(unsigned long long p) {
    float lo, hi;
    asm("mov.b64 {%0, %1}, %2;" : "=f"(lo), "=f"(hi) : "l"(p));
    return lo + hi;
}

// ---- dummy: keeps rec_kernel at process launch #4 for ncu capture ----
__global__ void dummy_kernel(int v) {
    if (threadIdx.x == 0 && blockIdx.x == 0) g_dummy = v;
}

// ---- Kernel 1: Xp[s][b][n] = b_out[n] + sum_i x[b][i][s] * Wx_out[i][n] ----
__global__ __launch_bounds__(256) void xproj_kernel(const float* __restrict__ x,
                                                    const float* __restrict__ Wx,
                                                    const float* __restrict__ bo) {
    __shared__ float xs[IN_DIM * 33];
    const int s = blockIdx.x;
    const int b0 = blockIdx.y * 32;
    const int t = threadIdx.x;
    const int b = t & 31;
    const int n0 = (t >> 5) * 64;

    for (int q = t; q < 32 * IN_DIM; q += 256) {
        int bb = q >> 6, i = q & 63;
        xs[i * 33 + bb] = x[((size_t)(b0 + bb) * IN_DIM + i) * S_LEN + s];
    }
    __syncthreads();

    float acc[64];
#pragma unroll
    for (int j = 0; j < 64; j++) acc[j] = 0.f;
#pragma unroll 2
    for (int k = 0; k < IN_DIM; k++) {
        float xv = xs[k * 33 + b];
        const float4* wr = (const float4*)(Wx + (size_t)k * G4 + n0);
#pragma unroll
        for (int j4 = 0; j4 < 16; j4++) {
            float4 w = __ldg(&wr[j4]);
            acc[4 * j4 + 0] = fmaf(xv, w.x, acc[4 * j4 + 0]);
            acc[4 * j4 + 1] = fmaf(xv, w.y, acc[4 * j4 + 1]);
            acc[4 * j4 + 2] = fmaf(xv, w.z, acc[4 * j4 + 2]);
            acc[4 * j4 + 3] = fmaf(xv, w.w, acc[4 * j4 + 3]);
        }
    }
#pragma unroll
    for (int j = 0; j < 64; j++) {
        g_Xp[((size_t)s * BATCH + b0 + b) * G4 + n0 + j] = acc[j] + __ldg(&bo[n0 + j]);
    }
}

// ---- Kernel 2: persistent recurrence (R7 structure); cluster of 4 CTAs = 1 group.
//      Register-resident weights, FFMA2, st.async + mbarrier exchange.
//      NEW: Xp double-buffered one step ahead; EW1 pushes before o_reg sigmoid. ----
__global__ __launch_bounds__(256, 1) __cluster_dims__(CPG, 1, 1)
void rec_kernel(const float* __restrict__ Wh_out,
                const float* __restrict__ Wx_in,
                const float* __restrict__ Wh_in,
                const float* __restrict__ b_in) {
    __shared__ __align__(16) float sh_h[BG * 2 * 68];     // staged h  [r][2 x 68]
    __shared__ __align__(16) float sh_xh[BG * 4 * 68];    // staged xh [r][4 x 68] (k'=2h interleave)
    __shared__ float sg[BG * 128];                        // gates [r][j]
    __shared__ __align__(8) unsigned long long mbars[2];  // [0]=xh, [1]=h
    __shared__ uint32_t ptab[CPG * 4];                    // per rank: xh, h, bx, bh

    const int cta = blockIdx.x;
    const int g   = cta >> 2;
    const int t   = threadIdx.x;
    const int j   = t >> 1;            // gate column 0..127
    const int kp  = t & 1;             // K-half
    uint32_t cs;
    asm("mov.u32 %0, %%cluster_ctarank;" : "=r"(cs));
    const int gcol = (j >> 5) * 128 + (int)cs * 32 + (j & 31);

    // ---- register-resident weights (R7 layout) ----
    unsigned long long wo[32];   // outer: k = kp*64 + 2q -> {Wh_out[k], Wh_out[k+1]}
    unsigned long long wi[64];   // inner: k' = kp*128 + 2q -> {Wx_in[h], Wh_in[h]}, h = kp*64 + q
    {
        const float* wbase = Wh_out + (size_t)(kp * 64) * G4 + gcol;
#pragma unroll
        for (int q = 0; q < 32; q++)
            wo[q] = pack2(wbase[(size_t)(2 * q) * G4], wbase[(size_t)(2 * q + 1) * G4]);
        const int hh0 = kp * 64;
#pragma unroll
        for (int q = 0; q < 64; q++)
            wi[q] = pack2(Wx_in[(size_t)(hh0 + q) * G4 + gcol],
                          Wh_in[(size_t)(hh0 + q) * G4 + gcol]);
    }
    const float bin = b_in[gcol];

    // peer address table + mbarrier init/arm
    if (t < CPG) {
        ptab[t * 4 + 0] = mapa_u32(smem_u32(sh_xh), t);
        ptab[t * 4 + 1] = mapa_u32(smem_u32(sh_h), t);
        ptab[t * 4 + 2] = mapa_u32(smem_u32(&mbars[0]), t);
        ptab[t * 4 + 3] = mapa_u32(smem_u32(&mbars[1]), t);
    }
    const uint32_t bx_loc = smem_u32(&mbars[0]);
    const uint32_t bh_loc = smem_u32(&mbars[1]);
    if (t == 0) {
        MBAR_INIT(bx_loc, 1);
        MBAR_INIT(bh_loc, 1);
        MBAR_ARM(bx_loc, 4096u);   // 4 ranks x 128 x 8B
        MBAR_ARM(bh_loc, 2048u);   // 4 ranks x 128 x 4B
    }
    for (int q = t; q < BG * 2 * 68; q += 256) sh_h[q] = 0.f;  // h0 = 0
    __syncthreads();
    CLUSTER_SYNC_();   // all peers' mbars initialized+armed before any st.async

    // owner role (t < 128): batch row bl, own hidden col
    const int bl = t >> 5, hc = t & 31;
    const int h_own = (int)cs * 32 + hc;
    const int kxi = 2 * h_own;
    const uint32_t offb_x = (uint32_t)(bl * 272 + (kxi >> 6) * 68 + (kxi & 63)) * 4u;
    const uint32_t offb_h = (uint32_t)(bl * 136 + (h_own >> 6) * 68 + (h_own & 63)) * 4u;
    float c_reg = 0.f, cn_reg = 0.f, o_reg = 0.f;

    const float* xp_base = g_Xp + (size_t)(g * BG) * G4 + gcol + (size_t)(kp * 2) * G4;

    // ---- Xp double buffer: current step's values preloaded ----
    float xpa = __ldcs(xp_base), xpb = __ldcs(xp_base + G4);

    for (int s = 0; s < S_LEN; s++) {
        const uint32_t par = (uint32_t)(s & 1);
        // issue next step's Xp loads early: full-step shadow (~6K cyc)
        const int sn = (s + 1 < S_LEN) ? s + 1 : s;
        const float* xpn = xp_base + (size_t)sn * BATCH * G4;
        float xna = __ldcs(xpn), xnb = __ldcs(xpn + G4);

        // ---- outer GEMM: K-half kp, 4 rows ----
        unsigned long long a0 = 0ull, a1 = 0ull, a2 = 0ull, a3 = 0ull;
        {
            const ulonglong2* h0 = (const ulonglong2*)(sh_h + 0 * 136 + kp * 68);
            const ulonglong2* h1 = (const ulonglong2*)(sh_h + 1 * 136 + kp * 68);
            const ulonglong2* h2 = (const ulonglong2*)(sh_h + 2 * 136 + kp * 68);
            const ulonglong2* h3 = (const ulonglong2*)(sh_h + 3 * 136 + kp * 68);
#pragma unroll
            for (int q2 = 0; q2 < 16; q2++) {
                ulonglong2 x0 = h0[q2], x1 = h1[q2], x2 = h2[q2], x3 = h3[q2];
                unsigned long long wA = wo[2 * q2], wB = wo[2 * q2 + 1];
                ffma2(a0, x0.x, wA); ffma2(a0, x0.y, wB);
                ffma2(a1, x1.x, wA); ffma2(a1, x1.y, wB);
                ffma2(a2, x2.x, wA); ffma2(a2, x2.y, wB);
                ffma2(a3, x3.x, wA); ffma2(a3, x3.y, wB);
            }
        }
        {
            float s0 = sum2(a0), s1 = sum2(a1), s2 = sum2(a2), s3 = sum2(a3);
            s0 += __shfl_xor_sync(0xffffffffu, s0, 1);
            s1 += __shfl_xor_sync(0xffffffffu, s1, 1);
            s2 += __shfl_xor_sync(0xffffffffu, s2, 1);
            s3 += __shfl_xor_sync(0xffffffffu, s3, 1);
            if (kp == 0) { sg[0 * 128 + j] = s0 + xpa; sg[1 * 128 + j] = s1 + xpb; }
            else         { sg[2 * 128 + j] = s2 + xpa; sg[3 * 128 + j] = s3 + xpb; }
        }
        __syncthreads();

        // ---- elementwise 1: push (x_in, h_in) first, o_reg sigmoid after ----
        if (t < 128) {
            float gi = sg[bl * 128 + hc];
            float gf = sg[bl * 128 + 32 + hc];
            float go = sg[bl * 128 + 64 + hc];
            float gg = sg[bl * 128 + 96 + hc];
            float xin = sigf(gi) * tanhf_fast(gg);
            float hin = sigf(gf) * c_reg;
#pragma unroll
            for (int r = 0; r < CPG; r++)
                st_async_v2f32(ptab[r * 4 + 0] + offb_x, ptab[r * 4 + 2], xin, hin);
            o_reg = sigf(go);   // computed in the shadow of the mbar wait
        }
        MBAR_WAIT(bx_loc, par);
        if (t == 0) MBAR_ARM(bx_loc, 4096u);

        // ---- inner GEMM: K'=256 interleaved, half per kp ----
        a0 = a1 = a2 = a3 = 0ull;
        {
            const ulonglong2* h0 = (const ulonglong2*)(sh_xh + 0 * 272 + 2 * kp * 68);
            const ulonglong2* h1 = (const ulonglong2*)(sh_xh + 1 * 272 + 2 * kp * 68);
            const ulonglong2* h2 = (const ulonglong2*)(sh_xh + 2 * 272 + 2 * kp * 68);
            const ulonglong2* h3 = (const ulonglong2*)(sh_xh + 3 * 272 + 2 * kp * 68);
#pragma unroll
            for (int q2 = 0; q2 < 16; q2++) {
                ulonglong2 x0 = h0[q2], x1 = h1[q2], x2 = h2[q2], x3 = h3[q2];
                unsigned long long wA = wi[2 * q2], wB = wi[2 * q2 + 1];
                ffma2(a0, x0.x, wA); ffma2(a0, x0.y, wB);
                ffma2(a1, x1.x, wA); ffma2(a1, x1.y, wB);
                ffma2(a2, x2.x, wA); ffma2(a2, x2.y, wB);
                ffma2(a3, x3.x, wA); ffma2(a3, x3.y, wB);
            }
#pragma unroll
            for (int q2 = 0; q2 < 16; q2++) {
                ulonglong2 x0 = h0[17 + q2], x1 = h1[17 + q2], x2 = h2[17 + q2], x3 = h3[17 + q2];
                unsigned long long wA = wi[32 + 2 * q2], wB = wi[33 + 2 * q2];
                ffma2(a0, x0.x, wA); ffma2(a0, x0.y, wB);
                ffma2(a1, x1.x, wA); ffma2(a1, x1.y, wB);
                ffma2(a2, x2.x, wA); ffma2(a2, x2.y, wB);
                ffma2(a3, x3.x, wA); ffma2(a3, x3.y, wB);
            }
        }
        {
            float s0 = sum2(a0), s1 = sum2(a1), s2 = sum2(a2), s3 = sum2(a3);
            s0 += __shfl_xor_sync(0xffffffffu, s0, 1);
            s1 += __shfl_xor_sync(0xffffffffu, s1, 1);
            s2 += __shfl_xor_sync(0xffffffffu, s2, 1);
            s3 += __shfl_xor_sync(0xffffffffu, s3, 1);
            if (kp == 0) { sg[0 * 128 + j] = s0 + bin; sg[1 * 128 + j] = s1 + bin; }
            else         { sg[2 * 128 + j] = s2 + bin; sg[3 * 128 + j] = s3 + bin; }
        }
        __syncthreads();

        // ---- elementwise 2: update state; push h to all 4 ranks ----
        if (t < 128) {
            float ii = sigf(sg[bl * 128 + hc]);
            float fi = sigf(sg[bl * 128 + 32 + hc]);
            float oi = sigf(sg[bl * 128 + 64 + hc]);
            float gg = tanhf_fast(sg[bl * 128 + 96 + hc]);
            cn_reg = fi * cn_reg + ii * gg;
            c_reg  = oi * tanhf_fast(cn_reg);
            float hnew = o_reg * tanhf_fast(c_reg);
#pragma unroll
            for (int r = 0; r < CPG; r++)
                st_async_f32(ptab[r * 4 + 1] + offb_h, ptab[r * 4 + 3], hnew);
            g_hs[((size_t)s * BATCH + g * BG + bl) * HID + h_own] = hnew;
        }
        MBAR_WAIT(bh_loc, par);
        if (t == 0) MBAR_ARM(bh_loc, 2048u);

        xpa = xna; xpb = xnb;   // rotate Xp double buffer
    }
    CLUSTER_SYNC_();
}

// ---- Kernel 3: out[b][s][o] = b_lin[o] + sum_h hs[s][b][h] * W_lin[o][h] ----
__global__ __launch_bounds__(256) void out_kernel(const float* __restrict__ Wl,
                                                  const float* __restrict__ bl,
                                                  float* __restrict__ out) {
    extern __shared__ float sm[];
    float* hsb = sm;               // transposed [h][b], pad 136
    float* wls = sm + 128 * 136;   // [h][o] pad 65

    const int s = blockIdx.x;
    const int t = threadIdx.x;
    const int o = t & 63;
    const int b0 = (t >> 6) * 32;

    const float* src = g_hs + (size_t)s * BATCH * HID;   // [b][h]
    for (int q = t; q < 16384; q += 256) {
        int b = q >> 7, h = q & 127;
        hsb[h * 136 + b] = src[q];
    }
    for (int q = t; q < 8192; q += 256) {
        int oo = q >> 7, k = q & 127;
        wls[k * 65 + oo] = Wl[q];
    }
    __syncthreads();

    float acc[32];
#pragma unroll
    for (int jj = 0; jj < 32; jj++) acc[jj] = 0.f;
#pragma unroll 2
    for (int k = 0; k < HID; k++) {
        float wv = wls[k * 65 + o];
        const float4* hr = (const float4*)(hsb + k * 136 + b0);
#pragma unroll
        for (int j4 = 0; j4 < 8; j4++) {
            float4 hv = hr[j4];
            acc[4 * j4 + 0] = fmaf(hv.x, wv, acc[4 * j4 + 0]);
            acc[4 * j4 + 1] = fmaf(hv.y, wv, acc[4 * j4 + 1]);
            acc[4 * j4 + 2] = fmaf(hv.z, wv, acc[4 * j4 + 2]);
            acc[4 * j4 + 3] = fmaf(hv.w, wv, acc[4 * j4 + 3]);
        }
    }
    float bb = bl[o];
#pragma unroll
    for (int jj = 0; jj < 32; jj++) {
        out[((size_t)(b0 + jj) * S_LEN + s) * OUT_DIM + o] = acc[jj] + bb;
    }
}

extern "C" void kernel_launch(void* const* d_in, const int* in_sizes, int n_in,
                              void* d_out, int out_size) {
    const float* x      = (const float*)d_in[0];
    const float* Wx_out = (const float*)d_in[1];
    const float* Wh_out = (const float*)d_in[2];
    const float* b_out  = (const float*)d_in[3];
    const float* Wx_in  = (const float*)d_in[4];
    const float* Wh_in  = (const float*)d_in[5];
    const float* b_in   = (const float*)d_in[6];
    const float* W_lin  = (const float*)d_in[7];
    const float* b_lin  = (const float*)d_in[8];
    float* out = (float*)d_out;

    cudaFuncSetAttribute(out_kernel, cudaFuncAttributeMaxDynamicSharedMemorySize, OUT_SMEM);

    dummy_kernel<<<1, 32>>>(1);                            // launch #1
    dummy_kernel<<<1, 32>>>(2);                            // launch #2
    xproj_kernel<<<dim3(S_LEN, BATCH / 32), 256>>>(x, Wx_out, b_out);  // #3
    rec_kernel<<<NCTA, 256>>>(Wh_out, Wx_in, Wh_in, b_in);             // #4 <- ncu slot
    out_kernel<<<S_LEN, 256, OUT_SMEM>>>(W_lin, b_lin, out);
}